// round 2
// baseline (speedup 1.0000x reference)
#include <cuda_runtime.h>

#define NN 50000
#define NE 800000
#define FIN 16
#define FE 8
#define HD 8
#define NG 512

// Scratch (allocation-free: __device__ globals).
// g_Y:    per-node factor table Y[n][o][a], 50000*64 f32 = 12.8MB (L2-resident)
// g_base: per-node base term base[n][o] (root path + biases), 1.6MB
// g_agg:  scatter-add accumulators for layer 1 / layer 2, 1.6MB each
__device__ float4 g_Y4[NN * 16];
__device__ float  g_base[NN * HD];
__device__ float  g_agg[2][NN * HD];

// Layer-1 per-node precompute, thread per (n,o): 400K threads.
//   Y1[n][o][a] = sum_i x[n,i] * We1[a, i*8+o]
//   base1[n][o] = b1[o] + sum_i x[n,i] * (root1[i,o] + be1[i*8+o])
// Also zeroes both agg buffers and seeds out with blast.
__global__ void k_node1(const float* __restrict__ x, const float* __restrict__ We1,
                        const float* __restrict__ be1, const float* __restrict__ root1,
                        const float* __restrict__ b1, const float* __restrict__ blast,
                        float* __restrict__ out) {
    __shared__ float sW[FIN * HD * HD];   // [i][o][a]
    __shared__ float sWc[FIN * HD];       // root1 + be1 : [i][o]
    for (int t = threadIdx.x; t < FIN * 64; t += blockDim.x) {
        int i = t >> 6, o = (t >> 3) & 7, a = t & 7;
        sW[t] = We1[a * (FIN * HD) + i * HD + o];
    }
    for (int t = threadIdx.x; t < FIN * HD; t += blockDim.x)
        sWc[t] = root1[t] + be1[t];
    __syncthreads();

    int gid = blockIdx.x * blockDim.x + threadIdx.x;
    if (gid < NG) out[gid] = blast[0];
    int n = gid >> 3, o = gid & 7;
    if (n >= NN) return;

    g_agg[0][gid] = 0.f;
    g_agg[1][gid] = 0.f;

    float xv[FIN];
    const float4* xp = (const float4*)(x + n * FIN);
    #pragma unroll
    for (int q = 0; q < 4; q++) {
        float4 v = xp[q];
        xv[q * 4 + 0] = v.x; xv[q * 4 + 1] = v.y;
        xv[q * 4 + 2] = v.z; xv[q * 4 + 3] = v.w;
    }

    float4 acc0 = make_float4(0.f, 0.f, 0.f, 0.f);
    float4 acc1 = make_float4(0.f, 0.f, 0.f, 0.f);
    float bacc = __ldg(b1 + o);
    const float4* sW4 = (const float4*)sW;
    #pragma unroll
    for (int i = 0; i < FIN; i++) {
        float xi = xv[i];
        float4 w0 = sW4[(i * HD + o) * 2 + 0];
        float4 w1 = sW4[(i * HD + o) * 2 + 1];
        acc0.x = fmaf(xi, w0.x, acc0.x); acc0.y = fmaf(xi, w0.y, acc0.y);
        acc0.z = fmaf(xi, w0.z, acc0.z); acc0.w = fmaf(xi, w0.w, acc0.w);
        acc1.x = fmaf(xi, w1.x, acc1.x); acc1.y = fmaf(xi, w1.y, acc1.y);
        acc1.z = fmaf(xi, w1.z, acc1.z); acc1.w = fmaf(xi, w1.w, acc1.w);
        bacc = fmaf(xi, sWc[i * HD + o], bacc);
    }

    g_Y4[n * 16 + o * 2 + 0] = acc0;
    g_Y4[n * 16 + o * 2 + 1] = acc1;
    g_base[gid] = bacc;
}

// Edge scatter: 2 threads per edge (halves o∈[0,4) / o∈[4,8)).
// Each thread gathers 128B of Y[src] (L2-resident), computes 4 dot-products,
// and issues ONE red.global.add.v4.f32 (vector L2 reduction, sm_90+).
__global__ void k_edge(const int* __restrict__ ei, const float* __restrict__ ea, int layer) {
    int gid = blockIdx.x * blockDim.x + threadIdx.x;
    int e = gid >> 1, half = gid & 1;
    int src = ei[e];
    int dst = ei[NE + e];
    const float4* eap = (const float4*)(ea + e * FE);
    float4 e0 = eap[0], e1 = eap[1];
    const float4* yp = g_Y4 + src * 16 + half * 8;
    float m[4];
    #pragma unroll
    for (int j = 0; j < 4; j++) {
        float4 y0 = yp[j * 2], y1 = yp[j * 2 + 1];
        m[j] = e0.x * y0.x + e0.y * y0.y + e0.z * y0.z + e0.w * y0.w
             + e1.x * y1.x + e1.y * y1.y + e1.z * y1.z + e1.w * y1.w;
    }
    float* agg = g_agg[layer] + dst * HD + half * 4;
    asm volatile("red.global.add.v4.f32 [%0], {%1, %2, %3, %4};"
                 :: "l"(agg), "f"(m[0]), "f"(m[1]), "f"(m[2]), "f"(m[3])
                 : "memory");
}

// h1 = relu(agg1 + base1); layer-2 per-node precompute, thread per (n,o):
//   Y2[n][o][a] = sum_i h1[i] * We2[a, i*8+o]
//   base2[n][o] = b2[o] + sum_i h1[i] * (root2[i,o] + be2[i*8+o])
// Overwrites g_Y4/g_base in place; readers & writers of a node's base are in
// the same warp, separated by __syncwarp().
__global__ void k_node2(const float* __restrict__ We2, const float* __restrict__ be2,
                        const float* __restrict__ root2, const float* __restrict__ b2) {
    __shared__ float sW[HD * HD * HD];    // [i][o][a]
    __shared__ float sWc[HD * HD];        // root2 + be2 : [i][o]
    for (int t = threadIdx.x; t < HD * 64; t += blockDim.x) {
        int i = t >> 6, o = (t >> 3) & 7, a = t & 7;
        sW[t] = We2[a * (HD * HD) + i * HD + o];
    }
    for (int t = threadIdx.x; t < HD * HD; t += blockDim.x)
        sWc[t] = root2[t] + be2[t];
    __syncthreads();

    int gid = blockIdx.x * blockDim.x + threadIdx.x;
    int n = gid >> 3, o = gid & 7;
    if (n >= NN) return;

    float h[HD];
    {
        const float4* ap = (const float4*)(g_agg[0] + n * HD);
        const float4* cp = (const float4*)(g_base + n * HD);
        float4 a0 = ap[0], a1 = ap[1], c0 = cp[0], c1 = cp[1];
        h[0] = fmaxf(a0.x + c0.x, 0.f); h[1] = fmaxf(a0.y + c0.y, 0.f);
        h[2] = fmaxf(a0.z + c0.z, 0.f); h[3] = fmaxf(a0.w + c0.w, 0.f);
        h[4] = fmaxf(a1.x + c1.x, 0.f); h[5] = fmaxf(a1.y + c1.y, 0.f);
        h[6] = fmaxf(a1.z + c1.z, 0.f); h[7] = fmaxf(a1.w + c1.w, 0.f);
    }
    __syncwarp();   // all readers of g_base[n][*] done before any writer below

    float4 acc0 = make_float4(0.f, 0.f, 0.f, 0.f);
    float4 acc1 = make_float4(0.f, 0.f, 0.f, 0.f);
    float bacc = __ldg(b2 + o);
    const float4* sW4 = (const float4*)sW;
    #pragma unroll
    for (int i = 0; i < HD; i++) {
        float hi = h[i];
        float4 w0 = sW4[(i * HD + o) * 2 + 0];
        float4 w1 = sW4[(i * HD + o) * 2 + 1];
        acc0.x = fmaf(hi, w0.x, acc0.x); acc0.y = fmaf(hi, w0.y, acc0.y);
        acc0.z = fmaf(hi, w0.z, acc0.z); acc0.w = fmaf(hi, w0.w, acc0.w);
        acc1.x = fmaf(hi, w1.x, acc1.x); acc1.y = fmaf(hi, w1.y, acc1.y);
        acc1.z = fmaf(hi, w1.z, acc1.z); acc1.w = fmaf(hi, w1.w, acc1.w);
        bacc = fmaf(hi, sWc[i * HD + o], bacc);
    }

    g_Y4[n * 16 + o * 2 + 0] = acc0;
    g_Y4[n * 16 + o * 2 + 1] = acc1;
    g_base[gid] = bacc;
}

// h2 = relu(agg2 + base2); out[batch[n]] += sum_o h2[o]*Wlast[o]
// (out pre-seeded with blast in k_node1)
__global__ void k_pool(const int* __restrict__ batch, const float* __restrict__ Wlast,
                       float* __restrict__ out) {
    int n = blockIdx.x * blockDim.x + threadIdx.x;
    if (n >= NN) return;
    const float4* ap = (const float4*)(g_agg[1] + n * HD);
    const float4* cp = (const float4*)(g_base + n * HD);
    float4 a0 = ap[0], a1 = ap[1], c0 = cp[0], c1 = cp[1];
    float s = fmaxf(a0.x + c0.x, 0.f) * __ldg(Wlast + 0)
            + fmaxf(a0.y + c0.y, 0.f) * __ldg(Wlast + 1)
            + fmaxf(a0.z + c0.z, 0.f) * __ldg(Wlast + 2)
            + fmaxf(a0.w + c0.w, 0.f) * __ldg(Wlast + 3)
            + fmaxf(a1.x + c1.x, 0.f) * __ldg(Wlast + 4)
            + fmaxf(a1.y + c1.y, 0.f) * __ldg(Wlast + 5)
            + fmaxf(a1.z + c1.z, 0.f) * __ldg(Wlast + 6)
            + fmaxf(a1.w + c1.w, 0.f) * __ldg(Wlast + 7);
    atomicAdd(out + batch[n], s);
}

extern "C" void kernel_launch(void* const* d_in, const int* in_sizes, int n_in,
                              void* d_out, int out_size) {
    const float* x     = (const float*)d_in[0];
    const int*   ei    = (const int*)  d_in[1];
    const float* ea    = (const float*)d_in[2];
    const int*   batch = (const int*)  d_in[3];
    const float* We1   = (const float*)d_in[4];
    const float* be1   = (const float*)d_in[5];
    const float* root1 = (const float*)d_in[6];
    const float* b1    = (const float*)d_in[7];
    const float* We2   = (const float*)d_in[8];
    const float* be2   = (const float*)d_in[9];
    const float* root2 = (const float*)d_in[10];
    const float* b2    = (const float*)d_in[11];
    const float* Wlast = (const float*)d_in[12];
    const float* blast = (const float*)d_in[13];
    float* out = (float*)d_out;

    k_node1<<<(NN * HD + 255) / 256, 256>>>(x, We1, be1, root1, b1, blast, out);
    k_edge <<<(NE * 2 + 255) / 256, 256>>>(ei, ea, 0);
    k_node2<<<(NN * HD + 255) / 256, 256>>>(We2, be2, root2, b2);
    k_edge <<<(NE * 2 + 255) / 256, 256>>>(ei, ea, 1);
    k_pool <<<(NN + 255) / 256, 256>>>(batch, Wlast, out);
}

// round 3
// speedup vs baseline: 1.6280x; 1.6280x over previous
#include <cuda_runtime.h>

#define NN 50000
#define NE 800000
#define FIN 16
#define FE 8
#define HD 8
#define NG 512

// Scratch (allocation-free: __device__ globals).
// g_Y4:   per-node factor table Y[n][o][a] (natural o order), 12.8MB, L2-resident
// g_base: per-node base term base[n][o] (natural o order)
// g_agg4: scatter accumulators, PERMUTED o order: slot s holds o(s) = (s>>1)+(s&1)*4
//         i.e. slots are [o0,o4,o1,o5,o2,o6,o3,o7]
__device__ float4 g_Y4[NN * 16];
__device__ float  g_base[NN * HD];
__device__ float4 g_agg4[2][NN * 2];

// Layer-1 per-node precompute, thread per (n,o). Also zeroes agg and seeds out.
//   Y1[n][o][a] = sum_i x[n,i] * We1[a, i*8+o]
//   base1[n][o] = b1[o] + sum_i x[n,i] * (root1[i,o] + be1[i*8+o])
__global__ void k_node1(const float* __restrict__ x, const float* __restrict__ We1,
                        const float* __restrict__ be1, const float* __restrict__ root1,
                        const float* __restrict__ b1, const float* __restrict__ blast,
                        float* __restrict__ out) {
    __shared__ float sW[FIN * HD * HD];   // [i][o][a]
    __shared__ float sWc[FIN * HD];       // root1 + be1 : [i][o]
    for (int t = threadIdx.x; t < FIN * 64; t += blockDim.x) {
        int i = t >> 6, o = (t >> 3) & 7, a = t & 7;
        sW[t] = We1[a * (FIN * HD) + i * HD + o];
    }
    for (int t = threadIdx.x; t < FIN * HD; t += blockDim.x)
        sWc[t] = root1[t] + be1[t];
    __syncthreads();

    int gid = blockIdx.x * blockDim.x + threadIdx.x;
    if (gid < NG) out[gid] = blast[0];
    if (gid < NN * 2) {
        float4 z = make_float4(0.f, 0.f, 0.f, 0.f);
        g_agg4[0][gid] = z;
        g_agg4[1][gid] = z;
    }
    int n = gid >> 3, o = gid & 7;
    if (n >= NN) return;

    float xv[FIN];
    const float4* xp = (const float4*)(x + n * FIN);
    #pragma unroll
    for (int q = 0; q < 4; q++) {
        float4 v = xp[q];
        xv[q * 4 + 0] = v.x; xv[q * 4 + 1] = v.y;
        xv[q * 4 + 2] = v.z; xv[q * 4 + 3] = v.w;
    }

    float4 acc0 = make_float4(0.f, 0.f, 0.f, 0.f);
    float4 acc1 = make_float4(0.f, 0.f, 0.f, 0.f);
    float bacc = __ldg(b1 + o);
    const float4* sW4 = (const float4*)sW;
    #pragma unroll
    for (int i = 0; i < FIN; i++) {
        float xi = xv[i];
        float4 w0 = sW4[(i * HD + o) * 2 + 0];
        float4 w1 = sW4[(i * HD + o) * 2 + 1];
        acc0.x = fmaf(xi, w0.x, acc0.x); acc0.y = fmaf(xi, w0.y, acc0.y);
        acc0.z = fmaf(xi, w0.z, acc0.z); acc0.w = fmaf(xi, w0.w, acc0.w);
        acc1.x = fmaf(xi, w1.x, acc1.x); acc1.y = fmaf(xi, w1.y, acc1.y);
        acc1.z = fmaf(xi, w1.z, acc1.z); acc1.w = fmaf(xi, w1.w, acc1.w);
        bacc = fmaf(xi, sWc[i * HD + o], bacc);
    }

    g_Y4[n * 16 + o * 2 + 0] = acc0;
    g_Y4[n * 16 + o * 2 + 1] = acc1;
    g_base[gid] = bacc;
}

// Edge scatter, 8 lanes/edge, line-disjoint loads (2 L1tex wavefronts/edge = floor).
// Lane r: y0 = row bytes [r*16, +16) (line 0), y1 = bytes [128+r*16, +16) (line 1).
//   y0 covers (o=r/2, a-half=r&1); y1 covers (o=4+r/2, same a-half).
// shfl_xor(1) combines halves -> lane r holds m[r/2] and m[4+r/2].
// Permuted agg layout makes those adjacent; lanes r=0,4 emit one red.v4 each.
__global__ void k_edge(const int* __restrict__ ei, const float* __restrict__ ea, int layer) {
    int gid = blockIdx.x * blockDim.x + threadIdx.x;
    int e = gid >> 3, r = gid & 7;
    int src = ei[e];
    int dst = ei[NE + e];
    float4 eh = *(const float4*)(ea + e * FE + (r & 1) * 4);
    const float* Yf = (const float*)g_Y4;
    float4 y0 = *(const float4*)(Yf + src * 64 + r * 4);
    float4 y1 = *(const float4*)(Yf + src * 64 + 32 + r * 4);
    float p0 = eh.x * y0.x + eh.y * y0.y + eh.z * y0.z + eh.w * y0.w;
    float p1 = eh.x * y1.x + eh.y * y1.y + eh.z * y1.z + eh.w * y1.w;
    p0 += __shfl_xor_sync(0xffffffffu, p0, 1);   // full m[r/2]
    p1 += __shfl_xor_sync(0xffffffffu, p1, 1);   // full m[4+r/2]
    int lane = threadIdx.x & 31;
    float g0 = __shfl_sync(0xffffffffu, p0, lane + 2);  // m[r/2+1]
    float g1 = __shfl_sync(0xffffffffu, p1, lane + 2);  // m[4+r/2+1]
    if ((r & 3) == 0) {
        // r=0: slots 0..3 = (m0,m4,m1,m5); r=4: slots 4..7 = (m2,m6,m3,m7)
        float* dp = (float*)(g_agg4[layer] + dst * 2) + r;
        asm volatile("red.global.add.v4.f32 [%0], {%1, %2, %3, %4};"
                     :: "l"(dp), "f"(p0), "f"(p1), "f"(g0), "f"(g1)
                     : "memory");
    }
}

// h1 = relu(agg1 + base1) [agg permuted]; layer-2 per-node precompute (thread per (n,o)).
__global__ void k_node2(const float* __restrict__ We2, const float* __restrict__ be2,
                        const float* __restrict__ root2, const float* __restrict__ b2) {
    __shared__ float sW[HD * HD * HD];    // [i][o][a]
    __shared__ float sWc[HD * HD];        // root2 + be2 : [i][o]
    for (int t = threadIdx.x; t < HD * 64; t += blockDim.x) {
        int i = t >> 6, o = (t >> 3) & 7, a = t & 7;
        sW[t] = We2[a * (HD * HD) + i * HD + o];
    }
    for (int t = threadIdx.x; t < HD * HD; t += blockDim.x)
        sWc[t] = root2[t] + be2[t];
    __syncthreads();

    int gid = blockIdx.x * blockDim.x + threadIdx.x;
    int n = gid >> 3, o = gid & 7;
    if (n >= NN) return;

    float h[HD];
    {
        float4 A0 = g_agg4[0][n * 2 + 0], A1 = g_agg4[0][n * 2 + 1];
        const float* cb = g_base + n * HD;
        // slot order: [o0,o4,o1,o5 | o2,o6,o3,o7]
        h[0] = fmaxf(A0.x + cb[0], 0.f); h[4] = fmaxf(A0.y + cb[4], 0.f);
        h[1] = fmaxf(A0.z + cb[1], 0.f); h[5] = fmaxf(A0.w + cb[5], 0.f);
        h[2] = fmaxf(A1.x + cb[2], 0.f); h[6] = fmaxf(A1.y + cb[6], 0.f);
        h[3] = fmaxf(A1.z + cb[3], 0.f); h[7] = fmaxf(A1.w + cb[7], 0.f);
    }
    __syncwarp();   // all reads of g_base[n][*] done before warp-mates overwrite

    float4 acc0 = make_float4(0.f, 0.f, 0.f, 0.f);
    float4 acc1 = make_float4(0.f, 0.f, 0.f, 0.f);
    float bacc = __ldg(b2 + o);
    const float4* sW4 = (const float4*)sW;
    #pragma unroll
    for (int i = 0; i < HD; i++) {
        float hi = h[i];
        float4 w0 = sW4[(i * HD + o) * 2 + 0];
        float4 w1 = sW4[(i * HD + o) * 2 + 1];
        acc0.x = fmaf(hi, w0.x, acc0.x); acc0.y = fmaf(hi, w0.y, acc0.y);
        acc0.z = fmaf(hi, w0.z, acc0.z); acc0.w = fmaf(hi, w0.w, acc0.w);
        acc1.x = fmaf(hi, w1.x, acc1.x); acc1.y = fmaf(hi, w1.y, acc1.y);
        acc1.z = fmaf(hi, w1.z, acc1.z); acc1.w = fmaf(hi, w1.w, acc1.w);
        bacc = fmaf(hi, sWc[i * HD + o], bacc);
    }

    g_Y4[n * 16 + o * 2 + 0] = acc0;
    g_Y4[n * 16 + o * 2 + 1] = acc1;
    g_base[gid] = bacc;
}

// h2 = relu(agg2 + base2) [agg permuted]; out[batch[n]] += sum_o h2[o]*Wlast[o]
__global__ void k_pool(const int* __restrict__ batch, const float* __restrict__ Wlast,
                       float* __restrict__ out) {
    int n = blockIdx.x * blockDim.x + threadIdx.x;
    if (n >= NN) return;
    float4 A0 = g_agg4[1][n * 2 + 0], A1 = g_agg4[1][n * 2 + 1];
    const float* cb = g_base + n * HD;
    float s = fmaxf(A0.x + cb[0], 0.f) * __ldg(Wlast + 0)
            + fmaxf(A0.y + cb[4], 0.f) * __ldg(Wlast + 4)
            + fmaxf(A0.z + cb[1], 0.f) * __ldg(Wlast + 1)
            + fmaxf(A0.w + cb[5], 0.f) * __ldg(Wlast + 5)
            + fmaxf(A1.x + cb[2], 0.f) * __ldg(Wlast + 2)
            + fmaxf(A1.y + cb[6], 0.f) * __ldg(Wlast + 6)
            + fmaxf(A1.z + cb[3], 0.f) * __ldg(Wlast + 3)
            + fmaxf(A1.w + cb[7], 0.f) * __ldg(Wlast + 7);
    atomicAdd(out + batch[n], s);
}

extern "C" void kernel_launch(void* const* d_in, const int* in_sizes, int n_in,
                              void* d_out, int out_size) {
    const float* x     = (const float*)d_in[0];
    const int*   ei    = (const int*)  d_in[1];
    const float* ea    = (const float*)d_in[2];
    const int*   batch = (const int*)  d_in[3];
    const float* We1   = (const float*)d_in[4];
    const float* be1   = (const float*)d_in[5];
    const float* root1 = (const float*)d_in[6];
    const float* b1    = (const float*)d_in[7];
    const float* We2   = (const float*)d_in[8];
    const float* be2   = (const float*)d_in[9];
    const float* root2 = (const float*)d_in[10];
    const float* b2    = (const float*)d_in[11];
    const float* Wlast = (const float*)d_in[12];
    const float* blast = (const float*)d_in[13];
    float* out = (float*)d_out;

    k_node1<<<(NN * HD + 255) / 256, 256>>>(x, We1, be1, root1, b1, blast, out);
    k_edge <<<(NE * 8) / 256, 256>>>(ei, ea, 0);
    k_node2<<<(NN * HD + 255) / 256, 256>>>(We2, be2, root2, b2);
    k_edge <<<(NE * 8) / 256, 256>>>(ei, ea, 1);
    k_pool <<<(NN + 255) / 256, 256>>>(batch, Wlast, out);
}

// round 4
// speedup vs baseline: 1.7110x; 1.0510x over previous
#include <cuda_runtime.h>

#define NN 50000
#define NE 800000
#define FIN 16
#define FE 8
#define HD 8
#define NG 512

// Scratch (allocation-free: __device__ globals).
// g_Yf: per-node factor table, LAYOUT [n][a_half][o][4]:
//       floats [n*64 + o*4 + j]      = Y[n][o][a=j]      (j=0..3)   -> line 0 of row
//       floats [n*64 + 32 + o*4 + j] = Y[n][o][a=4+j]               -> line 1 of row
//       12.8MB, L2-resident.
// g_base: per-node base term base[n][o], natural order.
// g_agg:  scatter accumulators, natural order [layer][n*8+o].
__device__ float g_Yf[NN * 64];
__device__ float g_base[NN * HD];
__device__ float g_agg[2][NN * HD];

// Layer-1 per-node precompute, thread per (n,o). Also zeroes agg and seeds out.
//   Y1[n][o][a] = sum_i x[n,i] * We1[a, i*8+o]
//   base1[n][o] = b1[o] + sum_i x[n,i] * (root1[i,o] + be1[i*8+o])
__global__ void k_node1(const float* __restrict__ x, const float* __restrict__ We1,
                        const float* __restrict__ be1, const float* __restrict__ root1,
                        const float* __restrict__ b1, const float* __restrict__ blast,
                        float* __restrict__ out) {
    __shared__ float sW[FIN * HD * HD];   // [i][o][a]
    __shared__ float sWc[FIN * HD];       // root1 + be1 : [i][o]
    for (int t = threadIdx.x; t < FIN * 64; t += blockDim.x) {
        int i = t >> 6, o = (t >> 3) & 7, a = t & 7;
        sW[t] = We1[a * (FIN * HD) + i * HD + o];
    }
    for (int t = threadIdx.x; t < FIN * HD; t += blockDim.x)
        sWc[t] = root1[t] + be1[t];
    __syncthreads();

    int gid = blockIdx.x * blockDim.x + threadIdx.x;
    if (gid < NG) out[gid] = blast[0];
    if (gid < NN * 2) {
        float4 z = make_float4(0.f, 0.f, 0.f, 0.f);
        ((float4*)g_agg[0])[gid] = z;
        ((float4*)g_agg[1])[gid] = z;
    }
    int n = gid >> 3, o = gid & 7;
    if (n >= NN) return;

    float xv[FIN];
    const float4* xp = (const float4*)(x + n * FIN);
    #pragma unroll
    for (int q = 0; q < 4; q++) {
        float4 v = xp[q];
        xv[q * 4 + 0] = v.x; xv[q * 4 + 1] = v.y;
        xv[q * 4 + 2] = v.z; xv[q * 4 + 3] = v.w;
    }

    float4 acc0 = make_float4(0.f, 0.f, 0.f, 0.f);   // a = 0..3
    float4 acc1 = make_float4(0.f, 0.f, 0.f, 0.f);   // a = 4..7
    float bacc = __ldg(b1 + o);
    const float4* sW4 = (const float4*)sW;
    #pragma unroll
    for (int i = 0; i < FIN; i++) {
        float xi = xv[i];
        float4 w0 = sW4[(i * HD + o) * 2 + 0];
        float4 w1 = sW4[(i * HD + o) * 2 + 1];
        acc0.x = fmaf(xi, w0.x, acc0.x); acc0.y = fmaf(xi, w0.y, acc0.y);
        acc0.z = fmaf(xi, w0.z, acc0.z); acc0.w = fmaf(xi, w0.w, acc0.w);
        acc1.x = fmaf(xi, w1.x, acc1.x); acc1.y = fmaf(xi, w1.y, acc1.y);
        acc1.z = fmaf(xi, w1.z, acc1.z); acc1.w = fmaf(xi, w1.w, acc1.w);
        bacc = fmaf(xi, sWc[i * HD + o], bacc);
    }

    *(float4*)(g_Yf + n * 64 + o * 4)      = acc0;
    *(float4*)(g_Yf + n * 64 + 32 + o * 4) = acc1;
    g_base[gid] = bacc;
}

// Edge scatter: 8 lanes per edge, 2 edges per thread (e and e+NE/2).
// Lane r loads Y[src][o=r][a0..3] (line 0) and Y[src][o=r][a4..7] (line 1):
// 2 L1tex wavefronts/edge (floor) and the dot is fully in-lane (no shfl).
// 3 independent shfls gather m[r+1..r+3] into lanes r=0,4 -> 2 red.v4/edge.
__global__ void k_edge(const int* __restrict__ ei, const float* __restrict__ ea, int layer) {
    int gid = blockIdx.x * blockDim.x + threadIdx.x;
    int r = gid & 7;
    int e0 = gid >> 3;            // [0, NE/2)
    int e1 = e0 + (NE / 2);

    int src0 = ei[e0],      dst0 = ei[NE + e0];
    int src1 = ei[e1],      dst1 = ei[NE + e1];
    float4 ea00 = *(const float4*)(ea + e0 * FE);
    float4 ea01 = *(const float4*)(ea + e0 * FE + 4);
    float4 ea10 = *(const float4*)(ea + e1 * FE);
    float4 ea11 = *(const float4*)(ea + e1 * FE + 4);
    float4 ya0 = *(const float4*)(g_Yf + src0 * 64 + r * 4);
    float4 yb0 = *(const float4*)(g_Yf + src0 * 64 + 32 + r * 4);
    float4 ya1 = *(const float4*)(g_Yf + src1 * 64 + r * 4);
    float4 yb1 = *(const float4*)(g_Yf + src1 * 64 + 32 + r * 4);

    float m0 = ea00.x * ya0.x + ea00.y * ya0.y + ea00.z * ya0.z + ea00.w * ya0.w
             + ea01.x * yb0.x + ea01.y * yb0.y + ea01.z * yb0.z + ea01.w * yb0.w;
    float m1 = ea10.x * ya1.x + ea10.y * ya1.y + ea10.z * ya1.z + ea10.w * ya1.w
             + ea11.x * yb1.x + ea11.y * yb1.y + ea11.z * yb1.z + ea11.w * yb1.w;

    const unsigned FULL = 0xffffffffu;
    int lane = threadIdx.x & 31;
    // 3 independent shuffles (depth 1); only lanes with r in {0,4} consume them,
    // and their sources (lane+1..3) stay inside the same 8-lane edge group.
    float m0a = __shfl_sync(FULL, m0, (lane + 1) & 31);
    float m0b = __shfl_sync(FULL, m0, (lane + 2) & 31);
    float m0c = __shfl_sync(FULL, m0, (lane + 3) & 31);
    float m1a = __shfl_sync(FULL, m1, (lane + 1) & 31);
    float m1b = __shfl_sync(FULL, m1, (lane + 2) & 31);
    float m1c = __shfl_sync(FULL, m1, (lane + 3) & 31);

    if ((r & 3) == 0) {
        float* p0 = g_agg[layer] + dst0 * HD + r;
        asm volatile("red.global.add.v4.f32 [%0], {%1, %2, %3, %4};"
                     :: "l"(p0), "f"(m0), "f"(m0a), "f"(m0b), "f"(m0c) : "memory");
        float* p1 = g_agg[layer] + dst1 * HD + r;
        asm volatile("red.global.add.v4.f32 [%0], {%1, %2, %3, %4};"
                     :: "l"(p1), "f"(m1), "f"(m1a), "f"(m1b), "f"(m1c) : "memory");
    }
}

// h1 = relu(agg1 + base1); layer-2 per-node precompute (thread per (n,o)).
//   Y2[n][o][a] = sum_i h1[i] * We2[a, i*8+o]   (written in [a_half][o][4] layout)
//   base2[n][o] = b2[o] + sum_i h1[i] * (root2[i,o] + be2[i*8+o])
__global__ void k_node2(const float* __restrict__ We2, const float* __restrict__ be2,
                        const float* __restrict__ root2, const float* __restrict__ b2) {
    __shared__ float sW[HD * HD * HD];    // [i][o][a]
    __shared__ float sWc[HD * HD];        // root2 + be2 : [i][o]
    for (int t = threadIdx.x; t < HD * 64; t += blockDim.x) {
        int i = t >> 6, o = (t >> 3) & 7, a = t & 7;
        sW[t] = We2[a * (HD * HD) + i * HD + o];
    }
    for (int t = threadIdx.x; t < HD * HD; t += blockDim.x)
        sWc[t] = root2[t] + be2[t];
    __syncthreads();

    int gid = blockIdx.x * blockDim.x + threadIdx.x;
    int n = gid >> 3, o = gid & 7;
    if (n >= NN) return;

    float h[HD];
    {
        const float4* ap = (const float4*)(g_agg[0] + n * HD);
        const float4* cp = (const float4*)(g_base + n * HD);
        float4 a0 = ap[0], a1 = ap[1], c0 = cp[0], c1 = cp[1];
        h[0] = fmaxf(a0.x + c0.x, 0.f); h[1] = fmaxf(a0.y + c0.y, 0.f);
        h[2] = fmaxf(a0.z + c0.z, 0.f); h[3] = fmaxf(a0.w + c0.w, 0.f);
        h[4] = fmaxf(a1.x + c1.x, 0.f); h[5] = fmaxf(a1.y + c1.y, 0.f);
        h[6] = fmaxf(a1.z + c1.z, 0.f); h[7] = fmaxf(a1.w + c1.w, 0.f);
    }
    __syncwarp();   // all reads of g_base[n][*] done before warp-mates overwrite

    float4 acc0 = make_float4(0.f, 0.f, 0.f, 0.f);
    float4 acc1 = make_float4(0.f, 0.f, 0.f, 0.f);
    float bacc = __ldg(b2 + o);
    const float4* sW4 = (const float4*)sW;
    #pragma unroll
    for (int i = 0; i < HD; i++) {
        float hi = h[i];
        float4 w0 = sW4[(i * HD + o) * 2 + 0];
        float4 w1 = sW4[(i * HD + o) * 2 + 1];
        acc0.x = fmaf(hi, w0.x, acc0.x); acc0.y = fmaf(hi, w0.y, acc0.y);
        acc0.z = fmaf(hi, w0.z, acc0.z); acc0.w = fmaf(hi, w0.w, acc0.w);
        acc1.x = fmaf(hi, w1.x, acc1.x); acc1.y = fmaf(hi, w1.y, acc1.y);
        acc1.z = fmaf(hi, w1.z, acc1.z); acc1.w = fmaf(hi, w1.w, acc1.w);
        bacc = fmaf(hi, sWc[i * HD + o], bacc);
    }

    *(float4*)(g_Yf + n * 64 + o * 4)      = acc0;
    *(float4*)(g_Yf + n * 64 + 32 + o * 4) = acc1;
    g_base[gid] = bacc;
}

// h2 = relu(agg2 + base2); out[batch[n]] += sum_o h2[o]*Wlast[o]
// (out pre-seeded with blast in k_node1)
__global__ void k_pool(const int* __restrict__ batch, const float* __restrict__ Wlast,
                       float* __restrict__ out) {
    int n = blockIdx.x * blockDim.x + threadIdx.x;
    if (n >= NN) return;
    const float4* ap = (const float4*)(g_agg[1] + n * HD);
    const float4* cp = (const float4*)(g_base + n * HD);
    float4 a0 = ap[0], a1 = ap[1], c0 = cp[0], c1 = cp[1];
    float s = fmaxf(a0.x + c0.x, 0.f) * __ldg(Wlast + 0)
            + fmaxf(a0.y + c0.y, 0.f) * __ldg(Wlast + 1)
            + fmaxf(a0.z + c0.z, 0.f) * __ldg(Wlast + 2)
            + fmaxf(a0.w + c0.w, 0.f) * __ldg(Wlast + 3)
            + fmaxf(a1.x + c1.x, 0.f) * __ldg(Wlast + 4)
            + fmaxf(a1.y + c1.y, 0.f) * __ldg(Wlast + 5)
            + fmaxf(a1.z + c1.z, 0.f) * __ldg(Wlast + 6)
            + fmaxf(a1.w + c1.w, 0.f) * __ldg(Wlast + 7);
    atomicAdd(out + batch[n], s);
}

extern "C" void kernel_launch(void* const* d_in, const int* in_sizes, int n_in,
                              void* d_out, int out_size) {
    const float* x     = (const float*)d_in[0];
    const int*   ei    = (const int*)  d_in[1];
    const float* ea    = (const float*)d_in[2];
    const int*   batch = (const int*)  d_in[3];
    const float* We1   = (const float*)d_in[4];
    const float* be1   = (const float*)d_in[5];
    const float* root1 = (const float*)d_in[6];
    const float* b1    = (const float*)d_in[7];
    const float* We2   = (const float*)d_in[8];
    const float* be2   = (const float*)d_in[9];
    const float* root2 = (const float*)d_in[10];
    const float* b2    = (const float*)d_in[11];
    const float* Wlast = (const float*)d_in[12];
    const float* blast = (const float*)d_in[13];
    float* out = (float*)d_out;

    k_node1<<<(NN * HD + 255) / 256, 256>>>(x, We1, be1, root1, b1, blast, out);
    k_edge <<<(NE / 2) * 8 / 256, 256>>>(ei, ea, 0);
    k_node2<<<(NN * HD + 255) / 256, 256>>>(We2, be2, root2, b2);
    k_edge <<<(NE / 2) * 8 / 256, 256>>>(ei, ea, 1);
    k_pool <<<(NN + 255) / 256, 256>>>(batch, Wlast, out);
}

// round 5
// speedup vs baseline: 1.8036x; 1.0541x over previous
#include <cuda_runtime.h>
#include <cuda_fp16.h>

#define NN 50000
#define NE 800000
#define FIN 16
#define FE 8
#define HD 8
#define NG 512

// Scratch (allocation-free: __device__ globals).
// g_Yh: per-node factor table in FP16, layout [n][o][a] as half:
//       row = 64 halves = 128 B = ONE cache line. Lane r's uint4 at
//       offset n*128 + r*16 covers o=r, a=0..7 completely (in-lane dot).
// g_base: per-node base term base[n][o], fp32 (precision-critical path).
// g_agg:  scatter accumulators, fp32, natural order [layer][n*8+o].
__device__ __half2 g_Yh[NN * 32];
__device__ float   g_base[NN * HD];
__device__ float   g_agg[2][NN * HD];

// Layer-1 per-node precompute, thread per (n,o). Also zeroes agg and seeds out.
//   Y1[n][o][a] = sum_i x[n,i] * We1[a, i*8+o]          (stored fp16)
//   base1[n][o] = b1[o] + sum_i x[n,i] * (root1[i,o] + be1[i*8+o])
__global__ void k_node1(const float* __restrict__ x, const float* __restrict__ We1,
                        const float* __restrict__ be1, const float* __restrict__ root1,
                        const float* __restrict__ b1, const float* __restrict__ blast,
                        float* __restrict__ out) {
    __shared__ float sW[FIN * HD * HD];   // [i][o][a]
    __shared__ float sWc[FIN * HD];       // root1 + be1 : [i][o]
    for (int t = threadIdx.x; t < FIN * 64; t += blockDim.x) {
        int i = t >> 6, o = (t >> 3) & 7, a = t & 7;
        sW[t] = We1[a * (FIN * HD) + i * HD + o];
    }
    for (int t = threadIdx.x; t < FIN * HD; t += blockDim.x)
        sWc[t] = root1[t] + be1[t];
    __syncthreads();

    int gid = blockIdx.x * blockDim.x + threadIdx.x;
    if (gid < NG) out[gid] = blast[0];
    if (gid < NN * 2) {
        float4 z = make_float4(0.f, 0.f, 0.f, 0.f);
        ((float4*)g_agg[0])[gid] = z;
        ((float4*)g_agg[1])[gid] = z;
    }
    int n = gid >> 3, o = gid & 7;
    if (n >= NN) return;

    float xv[FIN];
    const float4* xp = (const float4*)(x + n * FIN);
    #pragma unroll
    for (int q = 0; q < 4; q++) {
        float4 v = xp[q];
        xv[q * 4 + 0] = v.x; xv[q * 4 + 1] = v.y;
        xv[q * 4 + 2] = v.z; xv[q * 4 + 3] = v.w;
    }

    float4 acc0 = make_float4(0.f, 0.f, 0.f, 0.f);   // a = 0..3
    float4 acc1 = make_float4(0.f, 0.f, 0.f, 0.f);   // a = 4..7
    float bacc = __ldg(b1 + o);
    const float4* sW4 = (const float4*)sW;
    #pragma unroll
    for (int i = 0; i < FIN; i++) {
        float xi = xv[i];
        float4 w0 = sW4[(i * HD + o) * 2 + 0];
        float4 w1 = sW4[(i * HD + o) * 2 + 1];
        acc0.x = fmaf(xi, w0.x, acc0.x); acc0.y = fmaf(xi, w0.y, acc0.y);
        acc0.z = fmaf(xi, w0.z, acc0.z); acc0.w = fmaf(xi, w0.w, acc0.w);
        acc1.x = fmaf(xi, w1.x, acc1.x); acc1.y = fmaf(xi, w1.y, acc1.y);
        acc1.z = fmaf(xi, w1.z, acc1.z); acc1.w = fmaf(xi, w1.w, acc1.w);
        bacc = fmaf(xi, sWc[i * HD + o], bacc);
    }

    __half2 hy[4];
    hy[0] = __floats2half2_rn(acc0.x, acc0.y);
    hy[1] = __floats2half2_rn(acc0.z, acc0.w);
    hy[2] = __floats2half2_rn(acc1.x, acc1.y);
    hy[3] = __floats2half2_rn(acc1.z, acc1.w);
    *(uint4*)(g_Yh + n * 32 + o * 4) = *(const uint4*)hy;
    g_base[gid] = bacc;
}

// Edge scatter: 8 lanes/edge, 2 edges/thread (e and e+NE/2).
// Lane r loads ONE uint4 (16B) = full fp16 Y row slice for o=r:
// 1 L1tex wavefront per edge (floor for a 128B row). Dot fully in-lane.
// 3 independent shfls gather m[r+1..r+3] into lanes r=0,4 -> 2 red.v4/edge.
__global__ void k_edge(const int* __restrict__ ei, const float* __restrict__ ea, int layer) {
    int gid = blockIdx.x * blockDim.x + threadIdx.x;
    int r = gid & 7;
    int e0 = gid >> 3;            // [0, NE/2)
    int e1 = e0 + (NE / 2);

    int src0 = ei[e0], dst0 = ei[NE + e0];
    int src1 = ei[e1], dst1 = ei[NE + e1];
    float4 ea00 = *(const float4*)(ea + e0 * FE);
    float4 ea01 = *(const float4*)(ea + e0 * FE + 4);
    float4 ea10 = *(const float4*)(ea + e1 * FE);
    float4 ea11 = *(const float4*)(ea + e1 * FE + 4);
    uint4 yq0 = *(const uint4*)(g_Yh + src0 * 32 + r * 4);
    uint4 yq1 = *(const uint4*)(g_Yh + src1 * 32 + r * 4);

    const __half2* yh0 = (const __half2*)&yq0;
    const __half2* yh1 = (const __half2*)&yq1;
    float2 f00 = __half22float2(yh0[0]), f01 = __half22float2(yh0[1]);
    float2 f02 = __half22float2(yh0[2]), f03 = __half22float2(yh0[3]);
    float2 f10 = __half22float2(yh1[0]), f11 = __half22float2(yh1[1]);
    float2 f12 = __half22float2(yh1[2]), f13 = __half22float2(yh1[3]);

    float m0 = ea00.x * f00.x + ea00.y * f00.y + ea00.z * f01.x + ea00.w * f01.y
             + ea01.x * f02.x + ea01.y * f02.y + ea01.z * f03.x + ea01.w * f03.y;
    float m1 = ea10.x * f10.x + ea10.y * f10.y + ea10.z * f11.x + ea10.w * f11.y
             + ea11.x * f12.x + ea11.y * f12.y + ea11.z * f13.x + ea11.w * f13.y;

    const unsigned FULL = 0xffffffffu;
    int lane = threadIdx.x & 31;
    // 3 independent depth-1 shuffles; consumers (r=0,4) read lanes +1..+3
    // which stay inside the same 8-lane edge group.
    float m0a = __shfl_sync(FULL, m0, (lane + 1) & 31);
    float m0b = __shfl_sync(FULL, m0, (lane + 2) & 31);
    float m0c = __shfl_sync(FULL, m0, (lane + 3) & 31);
    float m1a = __shfl_sync(FULL, m1, (lane + 1) & 31);
    float m1b = __shfl_sync(FULL, m1, (lane + 2) & 31);
    float m1c = __shfl_sync(FULL, m1, (lane + 3) & 31);

    if ((r & 3) == 0) {
        float* p0 = g_agg[layer] + dst0 * HD + r;
        asm volatile("red.global.add.v4.f32 [%0], {%1, %2, %3, %4};"
                     :: "l"(p0), "f"(m0), "f"(m0a), "f"(m0b), "f"(m0c) : "memory");
        float* p1 = g_agg[layer] + dst1 * HD + r;
        asm volatile("red.global.add.v4.f32 [%0], {%1, %2, %3, %4};"
                     :: "l"(p1), "f"(m1), "f"(m1a), "f"(m1b), "f"(m1c) : "memory");
    }
}

// h1 = relu(agg1 + base1); layer-2 per-node precompute (thread per (n,o)).
//   Y2[n][o][a] = sum_i h1[i] * We2[a, i*8+o]   (stored fp16)
//   base2[n][o] = b2[o] + sum_i h1[i] * (root2[i,o] + be2[i*8+o])
__global__ void k_node2(const float* __restrict__ We2, const float* __restrict__ be2,
                        const float* __restrict__ root2, const float* __restrict__ b2) {
    __shared__ float sW[HD * HD * HD];    // [i][o][a]
    __shared__ float sWc[HD * HD];        // root2 + be2 : [i][o]
    for (int t = threadIdx.x; t < HD * 64; t += blockDim.x) {
        int i = t >> 6, o = (t >> 3) & 7, a = t & 7;
        sW[t] = We2[a * (HD * HD) + i * HD + o];
    }
    for (int t = threadIdx.x; t < HD * HD; t += blockDim.x)
        sWc[t] = root2[t] + be2[t];
    __syncthreads();

    int gid = blockIdx.x * blockDim.x + threadIdx.x;
    int n = gid >> 3, o = gid & 7;
    if (n >= NN) return;

    float h[HD];
    {
        const float4* ap = (const float4*)(g_agg[0] + n * HD);
        const float4* cp = (const float4*)(g_base + n * HD);
        float4 a0 = ap[0], a1 = ap[1], c0 = cp[0], c1 = cp[1];
        h[0] = fmaxf(a0.x + c0.x, 0.f); h[1] = fmaxf(a0.y + c0.y, 0.f);
        h[2] = fmaxf(a0.z + c0.z, 0.f); h[3] = fmaxf(a0.w + c0.w, 0.f);
        h[4] = fmaxf(a1.x + c1.x, 0.f); h[5] = fmaxf(a1.y + c1.y, 0.f);
        h[6] = fmaxf(a1.z + c1.z, 0.f); h[7] = fmaxf(a1.w + c1.w, 0.f);
    }
    __syncwarp();   // all reads of g_base[n][*] done before warp-mates overwrite

    float4 acc0 = make_float4(0.f, 0.f, 0.f, 0.f);
    float4 acc1 = make_float4(0.f, 0.f, 0.f, 0.f);
    float bacc = __ldg(b2 + o);
    const float4* sW4 = (const float4*)sW;
    #pragma unroll
    for (int i = 0; i < HD; i++) {
        float hi = h[i];
        float4 w0 = sW4[(i * HD + o) * 2 + 0];
        float4 w1 = sW4[(i * HD + o) * 2 + 1];
        acc0.x = fmaf(hi, w0.x, acc0.x); acc0.y = fmaf(hi, w0.y, acc0.y);
        acc0.z = fmaf(hi, w0.z, acc0.z); acc0.w = fmaf(hi, w0.w, acc0.w);
        acc1.x = fmaf(hi, w1.x, acc1.x); acc1.y = fmaf(hi, w1.y, acc1.y);
        acc1.z = fmaf(hi, w1.z, acc1.z); acc1.w = fmaf(hi, w1.w, acc1.w);
        bacc = fmaf(hi, sWc[i * HD + o], bacc);
    }

    __half2 hy[4];
    hy[0] = __floats2half2_rn(acc0.x, acc0.y);
    hy[1] = __floats2half2_rn(acc0.z, acc0.w);
    hy[2] = __floats2half2_rn(acc1.x, acc1.y);
    hy[3] = __floats2half2_rn(acc1.z, acc1.w);
    *(uint4*)(g_Yh + n * 32 + o * 4) = *(const uint4*)hy;
    g_base[gid] = bacc;
}

// h2 = relu(agg2 + base2); out[batch[n]] += sum_o h2[o]*Wlast[o]
// (out pre-seeded with blast in k_node1)
__global__ void k_pool(const int* __restrict__ batch, const float* __restrict__ Wlast,
                       float* __restrict__ out) {
    int n = blockIdx.x * blockDim.x + threadIdx.x;
    if (n >= NN) return;
    const float4* ap = (const float4*)(g_agg[1] + n * HD);
    const float4* cp = (const float4*)(g_base + n * HD);
    float4 a0 = ap[0], a1 = ap[1], c0 = cp[0], c1 = cp[1];
    float s = fmaxf(a0.x + c0.x, 0.f) * __ldg(Wlast + 0)
            + fmaxf(a0.y + c0.y, 0.f) * __ldg(Wlast + 1)
            + fmaxf(a0.z + c0.z, 0.f) * __ldg(Wlast + 2)
            + fmaxf(a0.w + c0.w, 0.f) * __ldg(Wlast + 3)
            + fmaxf(a1.x + c1.x, 0.f) * __ldg(Wlast + 4)
            + fmaxf(a1.y + c1.y, 0.f) * __ldg(Wlast + 5)
            + fmaxf(a1.z + c1.z, 0.f) * __ldg(Wlast + 6)
            + fmaxf(a1.w + c1.w, 0.f) * __ldg(Wlast + 7);
    atomicAdd(out + batch[n], s);
}

extern "C" void kernel_launch(void* const* d_in, const int* in_sizes, int n_in,
                              void* d_out, int out_size) {
    const float* x     = (const float*)d_in[0];
    const int*   ei    = (const int*)  d_in[1];
    const float* ea    = (const float*)d_in[2];
    const int*   batch = (const int*)  d_in[3];
    const float* We1   = (const float*)d_in[4];
    const float* be1   = (const float*)d_in[5];
    const float* root1 = (const float*)d_in[6];
    const float* b1    = (const float*)d_in[7];
    const float* We2   = (const float*)d_in[8];
    const float* be2   = (const float*)d_in[9];
    const float* root2 = (const float*)d_in[10];
    const float* b2    = (const float*)d_in[11];
    const float* Wlast = (const float*)d_in[12];
    const float* blast = (const float*)d_in[13];
    float* out = (float*)d_out;

    k_node1<<<(NN * HD + 255) / 256, 256>>>(x, We1, be1, root1, b1, blast, out);
    k_edge <<<(NE / 2) * 8 / 256, 256>>>(ei, ea, 0);
    k_node2<<<(NN * HD + 255) / 256, 256>>>(We2, be2, root2, b2);
    k_edge <<<(NE / 2) * 8 / 256, 256>>>(ei, ea, 1);
    k_pool <<<(NN + 255) / 256, 256>>>(batch, Wlast, out);
}

// round 6
// speedup vs baseline: 2.0207x; 1.1204x over previous
#include <cuda_runtime.h>
#include <cuda_fp16.h>

#define NN 50000
#define NE 800000
#define FIN 16
#define FE 8
#define HD 8
#define NG 512

// Scratch (allocation-free: __device__ globals).
// g_Yh: per-node factor table in FP16, layout [n][o][a] as half:
//       row = 64 halves = 128 B = ONE cache line. Lane r's uint4 at
//       offset n*128 + r*16 covers o=r, a=0..7 completely (in-lane dot).
// g_base: per-node base term base[n][o], fp32 (precision-critical path).
// g_agg:  scatter accumulators, fp32, natural order [layer][n*8+o].
__device__ __half2 g_Yh[NN * 32];
__device__ float   g_base[NN * HD];
__device__ float   g_agg[2][NN * HD];

// Layer-1 per-node precompute, thread per (n,o). Also zeroes agg and seeds out.
//   Y1[n][o][a] = sum_i x[n,i] * We1[a, i*8+o]          (stored fp16)
//   base1[n][o] = b1[o] + sum_i x[n,i] * (root1[i,o] + be1[i*8+o])
__global__ void k_node1(const float* __restrict__ x, const float* __restrict__ We1,
                        const float* __restrict__ be1, const float* __restrict__ root1,
                        const float* __restrict__ b1, const float* __restrict__ blast,
                        float* __restrict__ out) {
    __shared__ float sW[FIN * HD * HD];   // [i][o][a]
    __shared__ float sWc[FIN * HD];       // root1 + be1 : [i][o]
    for (int t = threadIdx.x; t < FIN * 64; t += blockDim.x) {
        int i = t >> 6, o = (t >> 3) & 7, a = t & 7;
        sW[t] = We1[a * (FIN * HD) + i * HD + o];
    }
    for (int t = threadIdx.x; t < FIN * HD; t += blockDim.x)
        sWc[t] = root1[t] + be1[t];
    __syncthreads();

    int gid = blockIdx.x * blockDim.x + threadIdx.x;
    if (gid < NG) out[gid] = blast[0];
    if (gid < NN * 2) {
        float4 z = make_float4(0.f, 0.f, 0.f, 0.f);
        ((float4*)g_agg[0])[gid] = z;
        ((float4*)g_agg[1])[gid] = z;
    }
    int n = gid >> 3, o = gid & 7;
    if (n >= NN) return;

    float xv[FIN];
    const float4* xp = (const float4*)(x + n * FIN);
    #pragma unroll
    for (int q = 0; q < 4; q++) {
        float4 v = xp[q];
        xv[q * 4 + 0] = v.x; xv[q * 4 + 1] = v.y;
        xv[q * 4 + 2] = v.z; xv[q * 4 + 3] = v.w;
    }

    float4 acc0 = make_float4(0.f, 0.f, 0.f, 0.f);   // a = 0..3
    float4 acc1 = make_float4(0.f, 0.f, 0.f, 0.f);   // a = 4..7
    float bacc = __ldg(b1 + o);
    const float4* sW4 = (const float4*)sW;
    #pragma unroll
    for (int i = 0; i < FIN; i++) {
        float xi = xv[i];
        float4 w0 = sW4[(i * HD + o) * 2 + 0];
        float4 w1 = sW4[(i * HD + o) * 2 + 1];
        acc0.x = fmaf(xi, w0.x, acc0.x); acc0.y = fmaf(xi, w0.y, acc0.y);
        acc0.z = fmaf(xi, w0.z, acc0.z); acc0.w = fmaf(xi, w0.w, acc0.w);
        acc1.x = fmaf(xi, w1.x, acc1.x); acc1.y = fmaf(xi, w1.y, acc1.y);
        acc1.z = fmaf(xi, w1.z, acc1.z); acc1.w = fmaf(xi, w1.w, acc1.w);
        bacc = fmaf(xi, sWc[i * HD + o], bacc);
    }

    __half2 hy[4];
    hy[0] = __floats2half2_rn(acc0.x, acc0.y);
    hy[1] = __floats2half2_rn(acc0.z, acc0.w);
    hy[2] = __floats2half2_rn(acc1.x, acc1.y);
    hy[3] = __floats2half2_rn(acc1.z, acc1.w);
    *(uint4*)(g_Yh + n * 32 + o * 4) = *(const uint4*)hy;
    g_base[gid] = bacc;
}

// Edge scatter: 8 lanes/edge, 2 edges/thread (e and e+NE/2).
// Lane r loads ONE uint4 (16B) = full fp16 Y row slice for o=r:
// 1 L1tex wavefront per edge (floor for a 128B row). Dot fully in-lane.
// 3 independent shfls gather m[r+1..r+3] into lanes r=0,4 -> 2 red.v4/edge.
// __launch_bounds__(256,4) gives ptxas ~64 regs so ALL gather loads stay
// in flight (MLP ~10) instead of serializing at 32 regs.
__global__ void __launch_bounds__(256, 4)
k_edge(const int* __restrict__ ei, const float* __restrict__ ea, int layer) {
    int gid = blockIdx.x * blockDim.x + threadIdx.x;
    int r = gid & 7;
    int e0 = gid >> 3;            // [0, NE/2)
    int e1 = e0 + (NE / 2);

    // src loads first: they head the dependent src->Y chain.
    int src0 = ei[e0];
    int src1 = ei[e1];
    int dst0 = ei[NE + e0];
    int dst1 = ei[NE + e1];
    // independent ea loads fill the shadow of the src loads
    float4 ea00 = *(const float4*)(ea + e0 * FE);
    float4 ea01 = *(const float4*)(ea + e0 * FE + 4);
    float4 ea10 = *(const float4*)(ea + e1 * FE);
    float4 ea11 = *(const float4*)(ea + e1 * FE + 4);
    uint4 yq0 = *(const uint4*)(g_Yh + src0 * 32 + r * 4);
    uint4 yq1 = *(const uint4*)(g_Yh + src1 * 32 + r * 4);

    const __half2* yh0 = (const __half2*)&yq0;
    const __half2* yh1 = (const __half2*)&yq1;
    float2 f00 = __half22float2(yh0[0]), f01 = __half22float2(yh0[1]);
    float2 f02 = __half22float2(yh0[2]), f03 = __half22float2(yh0[3]);
    float2 f10 = __half22float2(yh1[0]), f11 = __half22float2(yh1[1]);
    float2 f12 = __half22float2(yh1[2]), f13 = __half22float2(yh1[3]);

    float m0 = ea00.x * f00.x + ea00.y * f00.y + ea00.z * f01.x + ea00.w * f01.y
             + ea01.x * f02.x + ea01.y * f02.y + ea01.z * f03.x + ea01.w * f03.y;
    float m1 = ea10.x * f10.x + ea10.y * f10.y + ea10.z * f11.x + ea10.w * f11.y
             + ea11.x * f12.x + ea11.y * f12.y + ea11.z * f13.x + ea11.w * f13.y;

    const unsigned FULL = 0xffffffffu;
    int lane = threadIdx.x & 31;
    // 3 independent depth-1 shuffles; consumers (r=0,4) read lanes +1..+3
    // which stay inside the same 8-lane edge group.
    float m0a = __shfl_sync(FULL, m0, (lane + 1) & 31);
    float m0b = __shfl_sync(FULL, m0, (lane + 2) & 31);
    float m0c = __shfl_sync(FULL, m0, (lane + 3) & 31);
    float m1a = __shfl_sync(FULL, m1, (lane + 1) & 31);
    float m1b = __shfl_sync(FULL, m1, (lane + 2) & 31);
    float m1c = __shfl_sync(FULL, m1, (lane + 3) & 31);

    if ((r & 3) == 0) {
        float* p0 = g_agg[layer] + dst0 * HD + r;
        asm volatile("red.global.add.v4.f32 [%0], {%1, %2, %3, %4};"
                     :: "l"(p0), "f"(m0), "f"(m0a), "f"(m0b), "f"(m0c) : "memory");
        float* p1 = g_agg[layer] + dst1 * HD + r;
        asm volatile("red.global.add.v4.f32 [%0], {%1, %2, %3, %4};"
                     :: "l"(p1), "f"(m1), "f"(m1a), "f"(m1b), "f"(m1c) : "memory");
    }
}

// h1 = relu(agg1 + base1); layer-2 per-node precompute (thread per (n,o)).
//   Y2[n][o][a] = sum_i h1[i] * We2[a, i*8+o]   (stored fp16)
//   base2[n][o] = b2[o] + sum_i h1[i] * (root2[i,o] + be2[i*8+o])
__global__ void k_node2(const float* __restrict__ We2, const float* __restrict__ be2,
                        const float* __restrict__ root2, const float* __restrict__ b2) {
    __shared__ float sW[HD * HD * HD];    // [i][o][a]
    __shared__ float sWc[HD * HD];        // root2 + be2 : [i][o]
    for (int t = threadIdx.x; t < HD * 64; t += blockDim.x) {
        int i = t >> 6, o = (t >> 3) & 7, a = t & 7;
        sW[t] = We2[a * (HD * HD) + i * HD + o];
    }
    for (int t = threadIdx.x; t < HD * HD; t += blockDim.x)
        sWc[t] = root2[t] + be2[t];
    __syncthreads();

    int gid = blockIdx.x * blockDim.x + threadIdx.x;
    int n = gid >> 3, o = gid & 7;
    if (n >= NN) return;

    float h[HD];
    {
        const float4* ap = (const float4*)(g_agg[0] + n * HD);
        const float4* cp = (const float4*)(g_base + n * HD);
        float4 a0 = ap[0], a1 = ap[1], c0 = cp[0], c1 = cp[1];
        h[0] = fmaxf(a0.x + c0.x, 0.f); h[1] = fmaxf(a0.y + c0.y, 0.f);
        h[2] = fmaxf(a0.z + c0.z, 0.f); h[3] = fmaxf(a0.w + c0.w, 0.f);
        h[4] = fmaxf(a1.x + c1.x, 0.f); h[5] = fmaxf(a1.y + c1.y, 0.f);
        h[6] = fmaxf(a1.z + c1.z, 0.f); h[7] = fmaxf(a1.w + c1.w, 0.f);
    }
    __syncwarp();   // all reads of g_base[n][*] done before warp-mates overwrite

    float4 acc0 = make_float4(0.f, 0.f, 0.f, 0.f);
    float4 acc1 = make_float4(0.f, 0.f, 0.f, 0.f);
    float bacc = __ldg(b2 + o);
    const float4* sW4 = (const float4*)sW;
    #pragma unroll
    for (int i = 0; i < HD; i++) {
        float hi = h[i];
        float4 w0 = sW4[(i * HD + o) * 2 + 0];
        float4 w1 = sW4[(i * HD + o) * 2 + 1];
        acc0.x = fmaf(hi, w0.x, acc0.x); acc0.y = fmaf(hi, w0.y, acc0.y);
        acc0.z = fmaf(hi, w0.z, acc0.z); acc0.w = fmaf(hi, w0.w, acc0.w);
        acc1.x = fmaf(hi, w1.x, acc1.x); acc1.y = fmaf(hi, w1.y, acc1.y);
        acc1.z = fmaf(hi, w1.z, acc1.z); acc1.w = fmaf(hi, w1.w, acc1.w);
        bacc = fmaf(hi, sWc[i * HD + o], bacc);
    }

    __half2 hy[4];
    hy[0] = __floats2half2_rn(acc0.x, acc0.y);
    hy[1] = __floats2half2_rn(acc0.z, acc0.w);
    hy[2] = __floats2half2_rn(acc1.x, acc1.y);
    hy[3] = __floats2half2_rn(acc1.z, acc1.w);
    *(uint4*)(g_Yh + n * 32 + o * 4) = *(const uint4*)hy;
    g_base[gid] = bacc;
}

// h2 = relu(agg2 + base2); out[batch[n]] += sum_o h2[o]*Wlast[o].
// batch is SORTED -> warp-segmented shfl reduction, one atomic per
// (warp, graph-id) run instead of one per node (50K -> ~2K atomics).
__global__ void k_pool(const int* __restrict__ batch, const float* __restrict__ Wlast,
                       float* __restrict__ out) {
    int n = blockIdx.x * blockDim.x + threadIdx.x;
    int lane = threadIdx.x & 31;
    float s = 0.f;
    int bid = -1;
    if (n < NN) {
        bid = batch[n];
        const float4* ap = (const float4*)(g_agg[1] + n * HD);
        const float4* cp = (const float4*)(g_base + n * HD);
        float4 a0 = ap[0], a1 = ap[1], c0 = cp[0], c1 = cp[1];
        s = fmaxf(a0.x + c0.x, 0.f) * __ldg(Wlast + 0)
          + fmaxf(a0.y + c0.y, 0.f) * __ldg(Wlast + 1)
          + fmaxf(a0.z + c0.z, 0.f) * __ldg(Wlast + 2)
          + fmaxf(a0.w + c0.w, 0.f) * __ldg(Wlast + 3)
          + fmaxf(a1.x + c1.x, 0.f) * __ldg(Wlast + 4)
          + fmaxf(a1.y + c1.y, 0.f) * __ldg(Wlast + 5)
          + fmaxf(a1.z + c1.z, 0.f) * __ldg(Wlast + 6)
          + fmaxf(a1.w + c1.w, 0.f) * __ldg(Wlast + 7);
    }
    const unsigned FULL = 0xffffffffu;
    int bprev = __shfl_up_sync(FULL, bid, 1);
    // segmented suffix-sum over contiguous equal-bid runs (batch sorted)
    #pragma unroll
    for (int d = 1; d < 32; d <<= 1) {
        float t = __shfl_down_sync(FULL, s, d);
        int  tb = __shfl_down_sync(FULL, bid, d);
        if (lane + d < 32 && tb == bid) s += t;
    }
    bool leader = (n < NN) && (lane == 0 || bprev != bid);
    if (leader) atomicAdd(out + bid, s);
}

extern "C" void kernel_launch(void* const* d_in, const int* in_sizes, int n_in,
                              void* d_out, int out_size) {
    const float* x     = (const float*)d_in[0];
    const int*   ei    = (const int*)  d_in[1];
    const float* ea    = (const float*)d_in[2];
    const int*   batch = (const int*)  d_in[3];
    const float* We1   = (const float*)d_in[4];
    const float* be1   = (const float*)d_in[5];
    const float* root1 = (const float*)d_in[6];
    const float* b1    = (const float*)d_in[7];
    const float* We2   = (const float*)d_in[8];
    const float* be2   = (const float*)d_in[9];
    const float* root2 = (const float*)d_in[10];
    const float* b2    = (const float*)d_in[11];
    const float* Wlast = (const float*)d_in[12];
    const float* blast = (const float*)d_in[13];
    float* out = (float*)d_out;

    k_node1<<<(NN * HD + 255) / 256, 256>>>(x, We1, be1, root1, b1, blast, out);
    k_edge <<<(NE / 2) * 8 / 256, 256>>>(ei, ea, 0);
    k_node2<<<(NN * HD + 255) / 256, 256>>>(We2, be2, root2, b2);
    k_edge <<<(NE / 2) * 8 / 256, 256>>>(ei, ea, 1);
    k_pool <<<(NN + 255) / 256, 256>>>(batch, Wlast, out);
}